// round 12
// baseline (speedup 1.0000x reference)
#include <cuda_runtime.h>
#include <cuda_bf16.h>
#include <cstdint>

#define BATCH 64
#define VOCAB 50257
#define VP    50304          /* padded logits row stride (393*128) */
#define DIM   1024
#define NEGINF __int_as_float(0xff800000)

// ---------------- scratch (static __device__, no allocs) ----------------
__device__ float g_logits[(size_t)BATCH * VP];
__device__ float g_sums[BATCH];              // Sum exp(logit); zeroed by sample_kernel
__device__ int   g_hist[BATCH * 2048];       // per-row top-11-bit hist; zeroed by sample_kernel

// =========================================================================
// Kernel 1: HMMA bf16-split GEMM, double-buffered smem, 2 CTA/SM
// =========================================================================
#define TN   128
#define BK   32
#define NC   (DIM / BK)
#define SAST 40
#define ABUF (128 * SAST)
#define BBUF (256 * SAST)
#define BUFU16 (ABUF + BBUF)
#define GSMEM (2 * BUFU16 * 2)  /* 61440 B dynamic */

__device__ __forceinline__ uint32_t smem_u32(const void* p) {
    uint32_t a;
    asm("{ .reg .u64 t; cvta.to.shared.u64 t, %1; cvt.u32.u64 %0, t; }" : "=r"(a) : "l"(p));
    return a;
}

#define LDMX4(d, addr)                                                            \
    asm volatile("ldmatrix.sync.aligned.m8n8.x4.shared.b16 {%0,%1,%2,%3}, [%4];"  \
        : "=r"((d)[0]), "=r"((d)[1]), "=r"((d)[2]), "=r"((d)[3]) : "r"(addr))

#define MMA16816(c, a, b0, b1)                                                    \
    asm volatile("mma.sync.aligned.m16n8k16.row.col.f32.bf16.bf16.f32 "           \
        "{%0,%1,%2,%3}, {%4,%5,%6,%7}, {%8,%9}, {%0,%1,%2,%3};"                   \
        : "+f"((c)[0]), "+f"((c)[1]), "+f"((c)[2]), "+f"((c)[3])                  \
        : "r"((a)[0]), "r"((a)[1]), "r"((a)[2]), "r"((a)[3]), "r"(b0), "r"(b1))

__device__ __forceinline__ void split4(float4 v, uint2& hi, uint2& lo) {
    __nv_bfloat16 h0 = __float2bfloat16(v.x), h1 = __float2bfloat16(v.y);
    __nv_bfloat16 h2 = __float2bfloat16(v.z), h3 = __float2bfloat16(v.w);
    __nv_bfloat16 l0 = __float2bfloat16(v.x - __bfloat162float(h0));
    __nv_bfloat16 l1 = __float2bfloat16(v.y - __bfloat162float(h1));
    __nv_bfloat16 l2 = __float2bfloat16(v.z - __bfloat162float(h2));
    __nv_bfloat16 l3 = __float2bfloat16(v.w - __bfloat162float(h3));
    hi.x = ((uint32_t)__bfloat16_as_ushort(h1) << 16) | __bfloat16_as_ushort(h0);
    hi.y = ((uint32_t)__bfloat16_as_ushort(h3) << 16) | __bfloat16_as_ushort(h2);
    lo.x = ((uint32_t)__bfloat16_as_ushort(l1) << 16) | __bfloat16_as_ushort(l0);
    lo.y = ((uint32_t)__bfloat16_as_ushort(l3) << 16) | __bfloat16_as_ushort(l2);
}

__global__ __launch_bounds__(256, 2) void gemm_hmma_kernel(
    const float* __restrict__ H,
    const float* __restrict__ E,
    const float* __restrict__ temps)
{
    extern __shared__ __align__(16) uint16_t dynsm[];

    const int t    = threadIdx.x;
    const int lane = t & 31;
    const int wid  = t >> 5;
    const int n0   = blockIdx.x * TN;
    const int wm   = (wid >> 2) * 32;
    const int wn   = (wid & 3) * 32;

    float acc[2][4][4];
#pragma unroll
    for (int i = 0; i < 2; i++)
#pragma unroll
        for (int j = 0; j < 4; j++)
#pragma unroll
            for (int k = 0; k < 4; k++) acc[i][j][k] = 0.0f;

    float4 ra[2], rb[4];

    auto loadG = [&](int c) {
        const int k0 = c * BK;
#pragma unroll
        for (int i = 0; i < 2; i++) {
            int idx = t + i * 256;
            int r = idx >> 3, c4 = idx & 7;
            ra[i] = __ldg(reinterpret_cast<const float4*>(H + r * DIM + k0 + c4 * 4));
        }
#pragma unroll
        for (int i = 0; i < 4; i++) {
            int idx = t + i * 256;
            int r = idx >> 3, c4 = idx & 7;
            int gn = n0 + r;
            rb[i] = (gn < VOCAB)
                ? __ldg(reinterpret_cast<const float4*>(E + (size_t)gn * DIM + k0 + c4 * 4))
                : make_float4(0.f, 0.f, 0.f, 0.f);
        }
    };
    auto storeS = [&](int buf) {
        uint16_t* sA = dynsm + buf * BUFU16;
        uint16_t* sB = sA + ABUF;
#pragma unroll
        for (int i = 0; i < 2; i++) {
            int idx = t + i * 256;
            int r = idx >> 3, c4 = idx & 7;
            uint2 hi, lo;
            split4(ra[i], hi, lo);
            *reinterpret_cast<uint2*>(&sA[r * SAST + c4 * 4]) = hi;
            *reinterpret_cast<uint2*>(&sA[(r + 64) * SAST + c4 * 4]) = lo;
        }
#pragma unroll
        for (int i = 0; i < 4; i++) {
            int idx = t + i * 256;
            int r = idx >> 3, c4 = idx & 7;
            uint2 hi, lo;
            split4(rb[i], hi, lo);
            *reinterpret_cast<uint2*>(&sB[r * SAST + c4 * 4]) = hi;
            *reinterpret_cast<uint2*>(&sB[(r + 128) * SAST + c4 * 4]) = lo;
        }
    };

    const uint32_t dynBase = smem_u32(dynsm);
    const int rsel = (lane & 7) + ((lane >> 3) & 1) * 8;
    const int csel = (lane >> 4) * 8;

    loadG(0);
    storeS(0);
    __syncthreads();

    for (int c = 0; c < NC; c++) {
        if (c + 1 < NC) loadG(c + 1);

        const uint32_t aBase = dynBase + (uint32_t)(c & 1) * (BUFU16 * 2);
        const uint32_t bBase = aBase + ABUF * 2;
#pragma unroll
        for (int ks = 0; ks < 2; ks++) {
            uint32_t af[2][2][4];
#pragma unroll
            for (int fm = 0; fm < 2; fm++)
#pragma unroll
                for (int h = 0; h < 2; h++) {
                    uint32_t addr = aBase +
                        (uint32_t)(((h * 64 + wm + fm * 16 + rsel) * SAST) + ks * 16 + csel) * 2;
                    LDMX4(af[fm][h], addr);
                }
            uint32_t bf[2][2][4];
#pragma unroll
            for (int np = 0; np < 2; np++)
#pragma unroll
                for (int h = 0; h < 2; h++) {
                    uint32_t addr = bBase +
                        (uint32_t)(((h * 128 + wn + np * 16 + rsel) * SAST) + ks * 16 + csel) * 2;
                    LDMX4(bf[np][h], addr);
                }
#pragma unroll
            for (int fm = 0; fm < 2; fm++)
#pragma unroll
                for (int fn = 0; fn < 4; fn++) {
                    int np = fn >> 1, sb = fn & 1;
                    MMA16816(acc[fm][fn], af[fm][0], bf[np][0][sb], bf[np][0][sb + 2]); // hi*hi
                    MMA16816(acc[fm][fn], af[fm][1], bf[np][0][sb], bf[np][0][sb + 2]); // lo*hi
                    MMA16816(acc[fm][fn], af[fm][0], bf[np][1][sb], bf[np][1][sb + 2]); // hi*lo
                }
        }
        if (c + 1 < NC) storeS((c + 1) & 1);
        __syncthreads();
    }

    // ---- epilogue: /temp, pad-poison with -inf, store, exp-sum ----
#pragma unroll
    for (int fm = 0; fm < 2; fm++) {
        int m = wm + fm * 16 + (lane >> 2);
        float t0 = __ldg(temps + m);
        float t1 = __ldg(temps + m + 8);
        float s0 = 0.f, s1 = 0.f;
#pragma unroll
        for (int fn = 0; fn < 4; fn++) {
            int n = n0 + wn + fn * 8 + (lane & 3) * 2;
            bool v0ok = (n < VOCAB), v1ok = (n + 1 < VOCAB);
            float2 v0 = make_float2(v0ok ? acc[fm][fn][0] / t0 : NEGINF,
                                    v1ok ? acc[fm][fn][1] / t0 : NEGINF);
            float2 v1 = make_float2(v0ok ? acc[fm][fn][2] / t1 : NEGINF,
                                    v1ok ? acc[fm][fn][3] / t1 : NEGINF);
            *reinterpret_cast<float2*>(&g_logits[(size_t)m * VP + n]) = v0;
            *reinterpret_cast<float2*>(&g_logits[(size_t)(m + 8) * VP + n]) = v1;
            if (v0ok) { s0 += expf(v0.x); s1 += expf(v1.x); }
            if (v1ok) { s0 += expf(v0.y); s1 += expf(v1.y); }
        }
        s0 += __shfl_xor_sync(0xffffffffu, s0, 1);
        s0 += __shfl_xor_sync(0xffffffffu, s0, 2);
        s1 += __shfl_xor_sync(0xffffffffu, s1, 1);
        s1 += __shfl_xor_sync(0xffffffffu, s1, 2);
        if ((lane & 3) == 0) {
            atomicAdd(&g_sums[m], s0);
            atomicAdd(&g_sums[m + 8], s1);
        }
    }
}

// =========================================================================
// key mapping helpers
// =========================================================================
__device__ __forceinline__ unsigned fmap(float f) {
    unsigned u = __float_as_uint(f);
    return (u & 0x80000000u) ? ~u : (u | 0x80000000u);
}
__device__ __forceinline__ float funmap(unsigned u) {
    unsigned b = (u & 0x80000000u) ? (u & 0x7fffffffu) : ~u;
    return __uint_as_float(b);
}

// =========================================================================
// Kernel 2: sliced histogram + fprobs zeroing (grid: 4 slices x 64 rows)
// =========================================================================
#define NSLICE   4
#define SLICE_F4 (VP / 4 / NSLICE)     /* 3144 float4 per slice */
#define SLICE_EL (VP / NSLICE)         /* 12576 floats */

__global__ __launch_bounds__(1024) void hist_kernel(float* __restrict__ out_fprobs)
{
    const int s = blockIdx.x;
    const int b = blockIdx.y;
    const int t = threadIdx.x;

    __shared__ int s_hist[2048];
    for (int i = t; i < 2048; i += 1024) s_hist[i] = 0;

    // zero this slice of the fprobs row
    {
        float* fp = out_fprobs + (size_t)b * VOCAB;
        int lo = s * SLICE_EL;
        int hi = lo + SLICE_EL; if (hi > VOCAB) hi = VOCAB;
        for (int i = lo + t; i < hi; i += 1024) fp[i] = 0.0f;
    }
    __syncthreads();

    const float4* row4 = reinterpret_cast<const float4*>(g_logits + (size_t)b * VP);
    const int base = s * SLICE_F4;
    for (int i4 = t; i4 < SLICE_F4; i4 += 1024) {
        float4 v = row4[base + i4];
        atomicAdd(&s_hist[fmap(v.x) >> 21], 1);
        atomicAdd(&s_hist[fmap(v.y) >> 21], 1);
        atomicAdd(&s_hist[fmap(v.z) >> 21], 1);
        atomicAdd(&s_hist[fmap(v.w) >> 21], 1);
    }
    __syncthreads();

    int* gh = g_hist + b * 2048;
    for (int i = t; i < 2048; i += 1024) {
        int v = s_hist[i];
        if (v) atomicAdd(&gh[i], v);
    }
}

// =========================================================================
// Kernel 3: selection + single collect pass + top-p/top-k + JAX sample
// =========================================================================
__device__ __forceinline__ unsigned rotl32(unsigned x, int r) {
    return (x << r) | (x >> (32 - r));
}
__device__ __forceinline__ uint2 threefry_0_42(unsigned c0, unsigned c1) {
    const unsigned ks0 = 0u, ks1 = 42u;
    const unsigned ks2 = ks0 ^ ks1 ^ 0x1BD11BDAu;
    unsigned x0 = c0 + ks0;
    unsigned x1 = c1 + ks1;
#define TF_ROUND(r) { x0 += x1; x1 = rotl32(x1, r); x1 ^= x0; }
    TF_ROUND(13) TF_ROUND(15) TF_ROUND(26) TF_ROUND(6)
    x0 += ks1; x1 += ks2 + 1u;
    TF_ROUND(17) TF_ROUND(29) TF_ROUND(16) TF_ROUND(24)
    x0 += ks2; x1 += ks0 + 2u;
    TF_ROUND(13) TF_ROUND(15) TF_ROUND(26) TF_ROUND(6)
    x0 += ks0; x1 += ks1 + 3u;
    TF_ROUND(17) TF_ROUND(29) TF_ROUND(16) TF_ROUND(24)
    x0 += ks1; x1 += ks2 + 4u;
    TF_ROUND(13) TF_ROUND(15) TF_ROUND(26) TF_ROUND(6)
    x0 += ks2; x1 += ks0 + 5u;
#undef TF_ROUND
    return make_uint2(x0, x1);
}
__device__ __forceinline__ float jax_gumbel(unsigned i) {
    uint2 r = threefry_0_42(0u, i);
    unsigned bits = r.x ^ r.y;
    float f = __uint_as_float((bits >> 9) | 0x3f800000u) - 1.0f;
    float u = (f == 0.0f) ? 1.17549435e-38f : f;
    return -logf(-logf(u));
}

#define NCAND 2048
#define RANK  1000
#define NF4P  (VP / 4)       /* 12576: full padded row, no bounds checks */

__global__ __launch_bounds__(1024) void sample_kernel(
    const float* __restrict__ top_ps,
    const int*   __restrict__ top_ks,
    float* __restrict__ out_ids,
    float* __restrict__ out_lp,
    float* __restrict__ out_fprobs)
{
    const int b    = blockIdx.x;
    const int t    = threadIdx.x;
    const int lane = t & 31;
    const int wid  = t >> 5;
    const float* row = g_logits + (size_t)b * VP;
    const float4* row4 = reinterpret_cast<const float4*>(row);
    float* fp = out_fprobs + (size_t)b * VOCAB;
    int* gh = g_hist + b * 2048;

    const float logZ = logf(g_sums[b]);

    __shared__ unsigned long long s_keys[NCAND];
    __shared__ unsigned long long s_sel[NCAND];
    __shared__ int   s_hist[2048];
    __shared__ float s_wred[32];
    __shared__ int   s_widx[32];
    __shared__ int   s_sel1, s_rank2, s_sel2, s_cntHi, s_cntSel;

    // load global hist, then zero it for next replay
    for (int i = t; i < 2048; i += 1024) {
        s_hist[i] = gh[i];
        gh[i] = 0;
    }
    if (t == 0) { s_cntHi = 0; s_cntSel = 0; }
    __syncthreads();

    // warp 0: suffix-scan for sel1/rank2
    if (wid == 0) {
        int acc = 0;
        for (int base = 2048 - 32; base >= 0; base -= 32) {
            int bin = base + 31 - lane;
            int c = s_hist[bin];
            int p = c;
            for (int o = 1; o < 32; o <<= 1) {
                int v = __shfl_up_sync(0xffffffffu, p, o);
                if (lane >= o) p += v;
            }
            int S = acc + p;
            unsigned msk = __ballot_sync(0xffffffffu, S >= RANK);
            if (msk) {
                int l = __ffs(msk) - 1;
                int Ssel = __shfl_sync(0xffffffffu, S, l);
                int csel = __shfl_sync(0xffffffffu, c, l);
                if (lane == 0) {
                    s_sel1  = base + 31 - l;
                    s_rank2 = RANK - (Ssel - csel);
                }
                break;
            }
            acc += __shfl_sync(0xffffffffu, p, 31);
        }
    }
    __syncthreads();
    const int sel1 = s_sel1;
    const int rank2 = s_rank2;

    for (int i = t; i < 2048; i += 1024) s_hist[i] = 0;
    __syncthreads();

    // ---- single collect pass over padded row (pads are -inf, bin 3) ----
    for (int i4 = t; i4 < NF4P; i4 += 1024) {
        float4 v = row4[i4];
        int gi = i4 * 4;
        float e[4] = {v.x, v.y, v.z, v.w};
#pragma unroll
        for (int j = 0; j < 4; j++) {
            unsigned k = fmap(e[j]);
            int top11 = (int)(k >> 21);
            if (top11 > sel1) {
                int pos = atomicAdd(&s_cntHi, 1);   // bounded by RANK-1
                s_keys[pos] = ((unsigned long long)(~k) << 32) | (unsigned)(gi + j);
            } else if (top11 == sel1) {
                atomicAdd(&s_hist[(k >> 10) & 0x7FF], 1);
                int pos = atomicAdd(&s_cntSel, 1);
                if (pos < NCAND)
                    s_sel[pos] = ((unsigned long long)(~k) << 32) | (unsigned)(gi + j);
            }
        }
    }
    __syncthreads();

    // warp 0: suffix-scan for sel2
    if (wid == 0) {
        int acc = 0;
        for (int base = 2048 - 32; base >= 0; base -= 32) {
            int bin = base + 31 - lane;
            int c = s_hist[bin];
            int p = c;
            for (int o = 1; o < 32; o <<= 1) {
                int v = __shfl_up_sync(0xffffffffu, p, o);
                if (lane >= o) p += v;
            }
            int S = acc + p;
            unsigned msk = __ballot_sync(0xffffffffu, S >= rank2);
            if (msk) {
                int l = __ffs(msk) - 1;
                if (lane == 0) s_sel2 = base + 31 - l;
                break;
            }
            acc += __shfl_sync(0xffffffffu, p, 31);
        }
    }
    __syncthreads();
    const int sel2 = s_sel2;

    // ---- append sel-bucket keys with second-level bin >= sel2 ----
    int cntSel = s_cntSel; if (cntSel > NCAND) cntSel = NCAND;
    for (int i = t; i < cntSel; i += 1024) {
        unsigned long long key = s_sel[i];
        unsigned k = ~(unsigned)(key >> 32);
        if ((int)((k >> 10) & 0x7FF) >= sel2) {
            int pos = atomicAdd(&s_cntHi, 1);
            if (pos < NCAND) s_keys[pos] = key;
        }
    }
    __syncthreads();
    int cnt = s_cntHi; if (cnt > NCAND) cnt = NCAND;
    const int N = (cnt <= 1024) ? 1024 : NCAND;
    for (int i = t; i < N; i += 1024)
        if (i >= cnt) s_keys[i] = 0xFFFFFFFFFFFFFFFFull;
    __syncthreads();

    // ---- bitonic sort ascending (=> descending logit, stable ties) ----
    for (int k = 2; k <= N; k <<= 1) {
        for (int j = k >> 1; j > 0; j >>= 1) {
            for (int i = t; i < N; i += 1024) {
                int ixj = i ^ j;
                if (ixj > i) {
                    unsigned long long a = s_keys[i], c2 = s_keys[ixj];
                    bool asc = ((i & k) == 0);
                    if (asc ? (a > c2) : (a < c2)) {
                        s_keys[i] = c2;
                        s_keys[ixj] = a;
                    }
                }
            }
            __syncthreads();
        }
    }

    // ---- parallel top-p/top-k mask ----
    const int   K  = top_ks[b];
    const float tp = top_ps[b];
    const int limit = (cnt < K ? cnt : K);       // <= 999 < 1024

    float p = 0.f;
    int   idx = 0;
    const bool valid = (t < limit);
    if (valid) {
        unsigned long long key = s_keys[t];
        unsigned hi = (unsigned)(key >> 32);
        float logit = funmap(~hi);
        idx = (int)(unsigned)(key & 0xFFFFFFFFull);
        p = expf(logit - logZ);
    }
    // block-wide exclusive scan of p
    float x = p;
    for (int o = 1; o < 32; o <<= 1) {
        float v = __shfl_up_sync(0xffffffffu, x, o);
        if (lane >= o) x += v;
    }
    if (lane == 31) s_wred[wid] = x;
    __syncthreads();
    if (wid == 0) {
        float w = s_wred[lane];
        float y = w;
        for (int o = 1; o < 32; o <<= 1) {
            float v = __shfl_up_sync(0xffffffffu, y, o);
            if (lane >= o) y += v;
        }
        s_wred[lane] = y - w;
    }
    __syncthreads();
    float excl = s_wred[wid] + x - p;
    const bool survive = valid && (excl <= tp);

    // ---- scatter fprobs + gumbel argmax over survivors ----
    float best  = NEGINF;
    int   bestv = 0x7fffffff;
    if (survive) {
        fp[idx] = p;
        float g = jax_gumbel((unsigned)(b * VOCAB + idx));
        best  = logf(p) + g;
        bestv = idx;
    }
#pragma unroll
    for (int o = 16; o > 0; o >>= 1) {
        float ob = __shfl_xor_sync(0xffffffffu, best, o);
        int   ov = __shfl_xor_sync(0xffffffffu, bestv, o);
        if (ob > best || (ob == best && ov < bestv)) { best = ob; bestv = ov; }
    }
    if (lane == 0) { s_wred[wid] = best; s_widx[wid] = bestv; }
    __syncthreads();
    if (wid == 0) {
        best  = s_wred[lane];
        bestv = s_widx[lane];
#pragma unroll
        for (int o = 16; o > 0; o >>= 1) {
            float ob = __shfl_xor_sync(0xffffffffu, best, o);
            int   ov = __shfl_xor_sync(0xffffffffu, bestv, o);
            if (ob > best || (ob == best && ov < bestv)) { best = ob; bestv = ov; }
        }
        if (lane == 0) {
            out_ids[b] = (float)bestv;
            out_lp[b]  = row[bestv] - logZ;
            g_sums[b]  = 0.0f;   // reset for next graph replay
        }
    }
}

// =========================================================================
// launch
// =========================================================================
extern "C" void kernel_launch(void* const* d_in, const int* in_sizes, int n_in,
                              void* d_out, int out_size) {
    const float* H     = (const float*)d_in[0];
    const float* E     = (const float*)d_in[1];
    const float* temps = (const float*)d_in[2];
    const float* tps   = (const float*)d_in[3];
    const int*   tks   = (const int*)d_in[4];

    float* out = (float*)d_out;
    int fbase = out_size - BATCH * VOCAB;
    if (fbase < 0) fbase = 0;
    float* out_ids = out;
    float* out_lp  = out + ((fbase >= 2 * BATCH) ? BATCH : 0);
    float* out_fp  = out + fbase;

    cudaFuncSetAttribute(gemm_hmma_kernel,
                         cudaFuncAttributeMaxDynamicSharedMemorySize, GSMEM);

    gemm_hmma_kernel<<<(VOCAB + TN - 1) / TN, 256, GSMEM>>>(H, E, temps);
    hist_kernel<<<dim3(NSLICE, BATCH), 1024>>>(out_fp);
    sample_kernel<<<BATCH, 1024>>>(tps, tks, out_ids, out_lp, out_fp);
}